// round 15
// baseline (speedup 1.0000x reference)
#include <cuda_runtime.h>
#include <cuda_bf16.h>
#include <cstdint>
#include <math.h>

// Problem constants
constexpr int CB  = 2;     // batch
constexpr int CT  = 2048;  // seq len
constexpr int CH  = 2048;  // hidden
constexpr int CNH = 16;    // heads
constexpr int CHD = 128;   // head dim
constexpr int GM  = CB * CT;   // 4096
constexpr int GK  = CH;        // 2048
constexpr int GN  = CH;        // 2048

// ---------------------------------------------------------------------------
// Scratch (allocation-free: __device__ globals)
// ---------------------------------------------------------------------------
__device__ __align__(16) __nv_bfloat16 g_xh [(size_t)GM * GK];
__device__ __align__(16) __nv_bfloat16 g_xl [(size_t)GM * GK];
__device__ __align__(16) __nv_bfloat16 g_wh [4][(size_t)GN * GK];  // q,k,v,o
__device__ __align__(16) __nv_bfloat16 g_wl [4][(size_t)GN * GK];
__device__ __align__(16) __nv_bfloat16 g_qh [(size_t)CB * CNH * CT * CHD];  // scaled
__device__ __align__(16) __nv_bfloat16 g_ql [(size_t)CB * CNH * CT * CHD];
__device__ __align__(16) __nv_bfloat16 g_kh [(size_t)CB * CNH * CT * CHD];
__device__ __align__(16) __nv_bfloat16 g_kl [(size_t)CB * CNH * CT * CHD];
__device__ __align__(16) __nv_bfloat16 g_vh [(size_t)CB * CNH * CT * CHD];
__device__ __align__(16) __nv_bfloat16 g_vl [(size_t)CB * CNH * CT * CHD];
__device__ __align__(16) __nv_bfloat16 g_aoh[(size_t)GM * GK];  // attn out [B*T][H]
__device__ __align__(16) __nv_bfloat16 g_aol[(size_t)GM * GK];

// ---------------------------------------------------------------------------
// Baseline-ISA helpers (all valid on compute_103 virtual arch)
// ---------------------------------------------------------------------------
__device__ __forceinline__ uint32_t smem_to_u32(const void* p) {
    uint32_t a;
    asm("{ .reg .u64 t; cvta.to.shared.u64 t, %1; cvt.u32.u64 %0, t; }"
        : "=r"(a) : "l"(p));
    return a;
}
__device__ __forceinline__ void ldmx4(uint32_t* r, uint32_t addr) {
    asm volatile("ldmatrix.sync.aligned.m8n8.x4.shared.b16 {%0,%1,%2,%3}, [%4];"
        : "=r"(r[0]), "=r"(r[1]), "=r"(r[2]), "=r"(r[3]) : "r"(addr));
}
__device__ __forceinline__ void ldmx4t(uint32_t* r, uint32_t addr) {
    asm volatile("ldmatrix.sync.aligned.m8n8.x4.trans.shared.b16 {%0,%1,%2,%3}, [%4];"
        : "=r"(r[0]), "=r"(r[1]), "=r"(r[2]), "=r"(r[3]) : "r"(addr));
}
__device__ __forceinline__ void mma16816(float* d, const uint32_t* a,
                                         const uint32_t* b) {
    asm volatile(
        "mma.sync.aligned.m16n8k16.row.col.f32.bf16.bf16.f32 "
        "{%0,%1,%2,%3}, {%4,%5,%6,%7}, {%8,%9}, {%0,%1,%2,%3};"
        : "+f"(d[0]), "+f"(d[1]), "+f"(d[2]), "+f"(d[3])
        : "r"(a[0]), "r"(a[1]), "r"(a[2]), "r"(a[3]), "r"(b[0]), "r"(b[1]));
}
__device__ __forceinline__ void cp_async16(uint32_t dst, const void* src) {
    asm volatile("cp.async.cg.shared.global [%0], [%1], 16;"
        :: "r"(dst), "l"(src));
}
#define CP_COMMIT() asm volatile("cp.async.commit_group;" ::: "memory")
#define CP_WAIT0()  asm volatile("cp.async.wait_group 0;" ::: "memory")

__device__ __forceinline__ uint32_t pack_bf16(float a, float b) {
    __nv_bfloat162 h = __float22bfloat162_rn(make_float2(a, b));
    return *(uint32_t*)&h;
}

// ---------------------------------------------------------------------------
// Split conversion: hi = bf16(x), lo = bf16(x - hi)
// ---------------------------------------------------------------------------
__global__ void cvt_split_kernel(const float* __restrict__ src,
                                 __nv_bfloat16* __restrict__ hi,
                                 __nv_bfloat16* __restrict__ lo, int n4)
{
    int i = blockIdx.x * blockDim.x + threadIdx.x;
    if (i >= n4) return;
    float4 v = ((const float4*)src)[i];
    __nv_bfloat16 h[4], l[4];
    h[0] = __float2bfloat16(v.x); l[0] = __float2bfloat16(v.x - __bfloat162float(h[0]));
    h[1] = __float2bfloat16(v.y); l[1] = __float2bfloat16(v.y - __bfloat162float(h[1]));
    h[2] = __float2bfloat16(v.z); l[2] = __float2bfloat16(v.z - __bfloat162float(h[2]));
    h[3] = __float2bfloat16(v.w); l[3] = __float2bfloat16(v.w - __bfloat162float(h[3]));
    *(uint2*)(hi + (size_t)i * 4) = *(uint2*)h;
    *(uint2*)(lo + (size_t)i * 4) = *(uint2*)l;
}

// ---------------------------------------------------------------------------
// GEMM Y = A @ B^T, split-bf16 3-pass, cp.async 2-stage, 2 CTAs/SM.
// MODE 0: fp32 row-major [GM][GN] (Wo -> out), rows offset by bm_off.
// MODE 3: fused QKV (N = 3*GN), rows offset by bm_off (per-batch halves).
//         Per-CTA proj = bn>>11: Q/K -> acc via smem, RoPE (Q scaled),
//         split-bf16 into g_qh/ql/kh/kl; V -> split-bf16 into g_vh/vl.
// ---------------------------------------------------------------------------
constexpr int BKG = 32;
constexpr int ROWB = 80;                         // 64B data + 16 pad
constexpr int TILE_BYTES  = 128 * ROWB;          // 10240
constexpr int STAGE_BYTES = 4 * TILE_BYTES;      // Ah, Al, Bh, Bl
constexpr int SMEM_GEMM   = 2 * STAGE_BYTES;     // 81920 -> 2 CTAs/SM
constexpr int NKB = GK / BKG;                    // 64

template <int MODE>
__global__ __launch_bounds__(256, 2) void gemm_mma_kernel(
    const __nv_bfloat16* __restrict__ Ah, const __nv_bfloat16* __restrict__ Al,
    const __nv_bfloat16* __restrict__ Bh, const __nv_bfloat16* __restrict__ Bl,
    float* __restrict__ Y, const float* __restrict__ cosb,
    const float* __restrict__ sinb, int bm_off)
{
    extern __shared__ char sm[];
    const uint32_t sb = smem_to_u32(sm);
    const int tid = threadIdx.x;
    const int wid = tid >> 5, lid = tid & 31;
    const int wm = wid & 1, wn = wid >> 1;
    const int bn = blockIdx.x * 128, bm = blockIdx.y * 128 + bm_off;
    const int lg = lid >> 3, li = lid & 7;

    float acc[4][4][4];
#pragma unroll
    for (int mt = 0; mt < 4; mt++)
#pragma unroll
        for (int nt = 0; nt < 4; nt++)
#pragma unroll
            for (int r = 0; r < 4; r++) acc[mt][nt][r] = 0.f;

    auto issue_stage = [&](int s, int kb) {
#pragma unroll
        for (int i = 0; i < 8; i++) {
            int f = tid + i * 256;
            int pl = f >> 9, rem = f & 511, row = rem >> 2, c = rem & 3;
            const __nv_bfloat16* sp = (pl == 0) ? Ah : (pl == 1) ? Al
                                     : (pl == 2) ? Bh : Bl;
            int rbase = (pl >= 2) ? bn : bm;
            cp_async16(sb + s * STAGE_BYTES + pl * TILE_BYTES + row * ROWB + c * 16,
                       sp + (size_t)(rbase + row) * GK + kb * BKG + c * 8);
        }
    };

    issue_stage(0, 0); CP_COMMIT();

    for (int kb = 0; kb < NKB; kb++) {
        CP_WAIT0();
        __syncthreads();                  // stage kb ready; prev compute done
        if (kb + 1 < NKB) { issue_stage((kb + 1) & 1, kb + 1); CP_COMMIT(); }

        const uint32_t st = sb + (kb & 1) * STAGE_BYTES;
        const uint32_t sAh = st, sAl = st + TILE_BYTES;
        const uint32_t sBh = st + 2 * TILE_BYTES, sBl = st + 3 * TILE_BYTES;

#pragma unroll
        for (int ks = 0; ks < 2; ks++) {
            const int ko = ks * 32;
            const int aoff = ((lg & 1) * 8 + li) * ROWB + ko + (lg >> 1) * 16;
            const int boff = ((lg >> 1) * 8 + li) * ROWB + ko + (lg & 1) * 16;

            uint32_t ah[4][4], bh[4][2];
#pragma unroll
            for (int mt = 0; mt < 4; mt++)
                ldmx4(ah[mt], sAh + (wm * 64 + mt * 16) * ROWB + aoff);
#pragma unroll
            for (int p = 0; p < 2; p++) {
                uint32_t r[4];
                ldmx4(r, sBh + (wn * 32 + p * 16) * ROWB + boff);
                bh[2*p][0] = r[0]; bh[2*p][1] = r[1];
                bh[2*p+1][0] = r[2]; bh[2*p+1][1] = r[3];
            }
            // pass 1: Ah x Bh
#pragma unroll
            for (int mt = 0; mt < 4; mt++)
#pragma unroll
                for (int nt = 0; nt < 4; nt++)
                    mma16816(acc[mt][nt], ah[mt], bh[nt]);
            // pass 2: Al x Bh
            {
                uint32_t al[4][4];
#pragma unroll
                for (int mt = 0; mt < 4; mt++)
                    ldmx4(al[mt], sAl + (wm * 64 + mt * 16) * ROWB + aoff);
#pragma unroll
                for (int mt = 0; mt < 4; mt++)
#pragma unroll
                    for (int nt = 0; nt < 4; nt++)
                        mma16816(acc[mt][nt], al[mt], bh[nt]);
            }
            // pass 3: Ah x Bl
            {
                uint32_t bl[4][2];
#pragma unroll
                for (int p = 0; p < 2; p++) {
                    uint32_t r[4];
                    ldmx4(r, sBl + (wn * 32 + p * 16) * ROWB + boff);
                    bl[2*p][0] = r[0]; bl[2*p][1] = r[1];
                    bl[2*p+1][0] = r[2]; bl[2*p+1][1] = r[3];
                }
#pragma unroll
                for (int mt = 0; mt < 4; mt++)
#pragma unroll
                    for (int nt = 0; nt < 4; nt++)
                        mma16816(acc[mt][nt], ah[mt], bl[nt]);
            }
        }
    }

    const int er = lid >> 2;
    const int ec = (lid & 3) * 2;

    if (MODE == 0) {
#pragma unroll
        for (int mt = 0; mt < 4; mt++)
#pragma unroll
            for (int half = 0; half < 2; half++) {
                int row = bm + wm * 64 + mt * 16 + half * 8 + er;
                size_t base = (size_t)row * GN + bn;
#pragma unroll
                for (int nt = 0; nt < 4; nt++) {
                    int nc = wn * 32 + nt * 8 + ec;
                    *(float2*)(Y + base + nc) =
                        make_float2(acc[mt][nt][half * 2 + 0],
                                    acc[mt][nt][half * 2 + 1]);
                }
            }
    } else {  // MODE 3 fused QKV
        const int proj = bn >> 11;            // 0=Q, 1=K, 2=V (uniform per CTA)
        const int cn   = bn & (GN - 1);
        const int head = cn >> 7;
        if (proj == 2) {
#pragma unroll
            for (int mt = 0; mt < 4; mt++)
#pragma unroll
                for (int half = 0; half < 2; half++) {
                    int row = bm + wm * 64 + mt * 16 + half * 8 + er;
                    int b = row >> 11;
                    int t = row & (CT - 1);
                    size_t base = (((size_t)b * CNH + head) * CT + t) * CHD;
#pragma unroll
                    for (int nt = 0; nt < 4; nt++) {
                        int nc = wn * 32 + nt * 8 + ec;
                        float v0 = acc[mt][nt][half * 2 + 0];
                        float v1 = acc[mt][nt][half * 2 + 1];
                        __nv_bfloat162 h2 = __float22bfloat162_rn(make_float2(v0, v1));
                        *(uint32_t*)(g_vh + base + nc) = *(uint32_t*)&h2;
                        *(uint32_t*)(g_vl + base + nc) =
                            pack_bf16(v0 - __bfloat162float(h2.x),
                                      v1 - __bfloat162float(h2.y));
                    }
                }
        } else {
            // Q/K: stage fp32 tile in smem, apply RoPE, write split-bf16.
            float* smf = (float*)sm;          // [128][132] fp32 (67584 B)
            __syncthreads();                  // mainloop smem reads done
#pragma unroll
            for (int mt = 0; mt < 4; mt++)
#pragma unroll
                for (int half = 0; half < 2; half++) {
                    int rl = wm * 64 + mt * 16 + half * 8 + er;
#pragma unroll
                    for (int nt = 0; nt < 4; nt++) {
                        int cl = wn * 32 + nt * 8 + ec;
                        smf[rl * 132 + cl]     = acc[mt][nt][half * 2 + 0];
                        smf[rl * 132 + cl + 1] = acc[mt][nt][half * 2 + 1];
                    }
                }
            __syncthreads();
            const float scale = (proj == 0) ? 0.08838834764831843f : 1.f;
            __nv_bfloat16* Oh = (proj == 0) ? g_qh : g_kh;
            __nv_bfloat16* Ol = (proj == 0) ? g_ql : g_kl;
#pragma unroll
            for (int i = 0; i < 32; i++) {
                int idx = tid + i * 256;      // 8192 (row, d<64) pairs
                int rl = idx >> 6, d = idx & 63;
                int grow = bm + rl;
                int t = grow & (CT - 1), b = grow >> 11;
                float x0 = smf[rl * 132 + d];
                float x1 = smf[rl * 132 + d + 64];
                float c0 = cosb[t * CHD + d], c1 = cosb[t * CHD + d + 64];
                float s0 = sinb[t * CHD + d], s1 = sinb[t * CHD + d + 64];
                float ya = fmaf(x0, c0, -x1 * s0) * scale;
                float yb = fmaf(x1, c1,  x0 * s1) * scale;
                size_t base = (((size_t)b * CNH + head) * CT + t) * CHD;
                __nv_bfloat16 hh;
                hh = __float2bfloat16(ya);
                Oh[base + d] = hh;
                Ol[base + d] = __float2bfloat16(ya - __bfloat162float(hh));
                hh = __float2bfloat16(yb);
                Oh[base + d + 64] = hh;
                Ol[base + d + 64] = __float2bfloat16(yb - __bfloat162float(hh));
            }
        }
    }
}

// ---------------------------------------------------------------------------
// Tensor-core flash attention (causal). qt reversed (heavy first).
// Batch passed as param; per-batch launches pipeline with QKV/Wo.
// ---------------------------------------------------------------------------
constexpr int KROWB    = 272;                    // 256B data + 16 pad
constexpr int KV_PLANE = 64 * KROWB;             // 17408
constexpr int KV_STAGE = 4 * KV_PLANE;           // kh,kl,vh,vl
constexpr int SMEM_ATTN = 2 * KV_STAGE;          // 139264

__global__ __launch_bounds__(256) void attn_mma_kernel(int bparam)
{
    extern __shared__ char sm[];
    const uint32_t sb = smem_to_u32(sm);
    const int qt = gridDim.x - 1 - blockIdx.x;   // heavy first
    const int h = blockIdx.y, b = bparam;
    const int tid = threadIdx.x, w = tid >> 5, l = tid & 31;
    const size_t bh = ((size_t)b * CNH + h) * CT * CHD;
    const int fr = l >> 2, t2 = (l & 3) * 2;
    const int lg = l >> 3, li = l & 7;

    const __nv_bfloat16* qhp = g_qh + bh + (size_t)(qt * 128 + w * 16) * CHD;
    const __nv_bfloat16* qlp = g_ql + bh + (size_t)(qt * 128 + w * 16) * CHD;
    uint32_t qhf[8][4];
#pragma unroll
    for (int ks = 0; ks < 8; ks++) {
        int c = ks * 16 + t2;
        qhf[ks][0] = *(const uint32_t*)(qhp + fr * 128 + c);
        qhf[ks][1] = *(const uint32_t*)(qhp + (fr + 8) * 128 + c);
        qhf[ks][2] = *(const uint32_t*)(qhp + fr * 128 + c + 8);
        qhf[ks][3] = *(const uint32_t*)(qhp + (fr + 8) * 128 + c + 8);
    }

    float o[16][4];
#pragma unroll
    for (int nt = 0; nt < 16; nt++)
#pragma unroll
        for (int e = 0; e < 4; e++) o[nt][e] = 0.f;
    float mx[2] = {-1e30f, -1e30f}, ls[2] = {0.f, 0.f};

    const int last = 2 * qt + 1;

    auto issue = [&](int s, int kt) {
        const __nv_bfloat16* srcs[4] = {
            g_kh + bh + (size_t)kt * 64 * CHD, g_kl + bh + (size_t)kt * 64 * CHD,
            g_vh + bh + (size_t)kt * 64 * CHD, g_vl + bh + (size_t)kt * 64 * CHD};
#pragma unroll
        for (int i = 0; i < 16; i++) {
            int f = tid + i * 256;
            int pl = f >> 10, rem = f & 1023, row = rem >> 4, c = rem & 15;
            cp_async16(sb + s * KV_STAGE + pl * KV_PLANE + row * KROWB + c * 16,
                       srcs[pl] + row * 128 + c * 8);
        }
    };

    issue(0, 0); CP_COMMIT();

    for (int kt = 0; kt <= last; kt++) {
        CP_WAIT0();
        __syncthreads();           // stage kt visible; all warps done with kt-1
        if (kt < last) { issue((kt + 1) & 1, kt + 1); CP_COMMIT(); }

        const uint32_t st = sb + (kt & 1) * KV_STAGE;
        const uint32_t kh_s = st, kl_s = st + KV_PLANE;
        const uint32_t vh_s = st + 2 * KV_PLANE, vl_s = st + 3 * KV_PLANE;

        // ---- S = Qs @ K^T (3 passes) ----
        float s4[8][4];
#pragma unroll
        for (int nt = 0; nt < 8; nt++)
#pragma unroll
            for (int e = 0; e < 4; e++) s4[nt][e] = 0.f;

        const int boffb = ((lg >> 1) * 8 + li) * KROWB + (lg & 1) * 16;
#pragma unroll
        for (int ks = 0; ks < 8; ks++) {
            uint32_t bf[8][2];
#pragma unroll
            for (int p = 0; p < 4; p++) {
                uint32_t r[4];
                ldmx4(r, kh_s + p * 16 * KROWB + ks * 32 + boffb);
                bf[2*p][0] = r[0]; bf[2*p][1] = r[1];
                bf[2*p+1][0] = r[2]; bf[2*p+1][1] = r[3];
            }
#pragma unroll
            for (int nt = 0; nt < 8; nt++) mma16816(s4[nt], qhf[ks], bf[nt]);
            uint32_t qlf[4];
            int c = ks * 16 + t2;
            qlf[0] = *(const uint32_t*)(qlp + fr * 128 + c);
            qlf[1] = *(const uint32_t*)(qlp + (fr + 8) * 128 + c);
            qlf[2] = *(const uint32_t*)(qlp + fr * 128 + c + 8);
            qlf[3] = *(const uint32_t*)(qlp + (fr + 8) * 128 + c + 8);
#pragma unroll
            for (int nt = 0; nt < 8; nt++) mma16816(s4[nt], qlf, bf[nt]);
        }
#pragma unroll
        for (int ks = 0; ks < 8; ks++) {
            uint32_t bf[8][2];
#pragma unroll
            for (int p = 0; p < 4; p++) {
                uint32_t r[4];
                ldmx4(r, kl_s + p * 16 * KROWB + ks * 32 + boffb);
                bf[2*p][0] = r[0]; bf[2*p][1] = r[1];
                bf[2*p+1][0] = r[2]; bf[2*p+1][1] = r[3];
            }
#pragma unroll
            for (int nt = 0; nt < 8; nt++) mma16816(s4[nt], qhf[ks], bf[nt]);
        }

        // ---- causal mask ----
        if (kt >= 2 * qt) {
            int row0 = qt * 128 + w * 16 + fr;
#pragma unroll
            for (int nt = 0; nt < 8; nt++) {
                int col0 = kt * 64 + nt * 8 + t2;
#pragma unroll
                for (int e = 0; e < 4; e++) {
                    int row = row0 + 8 * (e >> 1);
                    int col = col0 + (e & 1);
                    if (col > row) s4[nt][e] = -1e30f;
                }
            }
        }

        // ---- online softmax ----
#pragma unroll
        for (int half = 0; half < 2; half++) {
            float rm = -1e30f;
#pragma unroll
            for (int nt = 0; nt < 8; nt++)
                rm = fmaxf(rm, fmaxf(s4[nt][2*half], s4[nt][2*half+1]));
            rm = fmaxf(rm, __shfl_xor_sync(0xffffffffu, rm, 1));
            rm = fmaxf(rm, __shfl_xor_sync(0xffffffffu, rm, 2));
            float mn = fmaxf(mx[half], rm);
            float al = __expf(mx[half] - mn);
            mx[half] = mn;
            float rs = 0.f;
#pragma unroll
            for (int nt = 0; nt < 8; nt++) {
                s4[nt][2*half]   = __expf(s4[nt][2*half]   - mn);
                s4[nt][2*half+1] = __expf(s4[nt][2*half+1] - mn);
                rs += s4[nt][2*half] + s4[nt][2*half+1];
            }
            rs += __shfl_xor_sync(0xffffffffu, rs, 1);
            rs += __shfl_xor_sync(0xffffffffu, rs, 2);
            ls[half] = ls[half] * al + rs;
#pragma unroll
            for (int nt = 0; nt < 16; nt++) {
                o[nt][2*half]   *= al;
                o[nt][2*half+1] *= al;
            }
        }

        // ---- P fragments (hi/lo) ----
        uint32_t pha[4][4], pla[4][4];
#pragma unroll
        for (int kc = 0; kc < 4; kc++) {
#pragma unroll
            for (int j = 0; j < 4; j++) {
                int nt = 2 * kc + (j >> 1);
                int eb = (j & 1) * 2;
                float x0 = s4[nt][eb], x1 = s4[nt][eb + 1];
                __nv_bfloat162 h2 = __float22bfloat162_rn(make_float2(x0, x1));
                pha[kc][j] = *(uint32_t*)&h2;
                pla[kc][j] = pack_bf16(x0 - __bfloat162float(h2.x),
                                       x1 - __bfloat162float(h2.y));
            }
        }

        // ---- O += P @ V (3 passes) ----
#pragma unroll
        for (int kc = 0; kc < 4; kc++) {
            uint32_t vb[16][2];
#pragma unroll
            for (int p = 0; p < 8; p++) {
                uint32_t r[4];
                uint32_t addr = vh_s + (kc * 16 + (lg & 1) * 8 + li) * KROWB
                                + (p * 16 + (lg >> 1) * 8) * 2;
                ldmx4t(r, addr);
                vb[2*p][0] = r[0]; vb[2*p][1] = r[1];
                vb[2*p+1][0] = r[2]; vb[2*p+1][1] = r[3];
            }
#pragma unroll
            for (int nt = 0; nt < 16; nt++) mma16816(o[nt], pha[kc], vb[nt]);
#pragma unroll
            for (int nt = 0; nt < 16; nt++) mma16816(o[nt], pla[kc], vb[nt]);
#pragma unroll
            for (int p = 0; p < 8; p++) {
                uint32_t r[4];
                uint32_t addr = vl_s + (kc * 16 + (lg & 1) * 8 + li) * KROWB
                                + (p * 16 + (lg >> 1) * 8) * 2;
                ldmx4t(r, addr);
                vb[2*p][0] = r[0]; vb[2*p][1] = r[1];
                vb[2*p+1][0] = r[2]; vb[2*p+1][1] = r[3];
            }
#pragma unroll
            for (int nt = 0; nt < 16; nt++) mma16816(o[nt], pha[kc], vb[nt]);
        }
    }

    // ---- epilogue ----
    float inv0 = 1.f / ls[0], inv1 = 1.f / ls[1];
    int row0 = qt * 128 + w * 16 + fr;
    size_t r0 = ((size_t)b * CT + row0) * CH + h * CHD;
    size_t r1 = ((size_t)b * CT + row0 + 8) * CH + h * CHD;
#pragma unroll
    for (int nt = 0; nt < 16; nt++) {
        int col = nt * 8 + t2;
        float v0 = o[nt][0] * inv0, v1 = o[nt][1] * inv0;
        __nv_bfloat162 h2 = __float22bfloat162_rn(make_float2(v0, v1));
        *(uint32_t*)(g_aoh + r0 + col) = *(uint32_t*)&h2;
        *(uint32_t*)(g_aol + r0 + col) =
            pack_bf16(v0 - __bfloat162float(h2.x), v1 - __bfloat162float(h2.y));
        float v2 = o[nt][2] * inv1, v3 = o[nt][3] * inv1;
        __nv_bfloat162 h3 = __float22bfloat162_rn(make_float2(v2, v3));
        *(uint32_t*)(g_aoh + r1 + col) = *(uint32_t*)&h3;
        *(uint32_t*)(g_aol + r1 + col) =
            pack_bf16(v2 - __bfloat162float(h3.x), v3 - __bfloat162float(h3.y));
    }
}

// ---------------------------------------------------------------------------
// Launch — 4-stage pipeline:
//   QKV(b0) -> { QKV(b1) || attn(b0) } -> { attn(b1) || Wo(b0) } -> Wo(b1)
// Every launch tail after the first is backfilled by independent next-phase
// work. Prologue: x-cvt split by batch across streams.
// ---------------------------------------------------------------------------
extern "C" void kernel_launch(void* const* d_in, const int* in_sizes, int n_in,
                              void* d_out, int out_size)
{
    (void)in_sizes; (void)n_in; (void)out_size;
    const float* x    = (const float*)d_in[0];
    const float* cosb = (const float*)d_in[1];
    const float* sinb = (const float*)d_in[2];
    const float* Wq   = (const float*)d_in[3];
    const float* Wk   = (const float*)d_in[4];
    const float* Wv   = (const float*)d_in[5];
    const float* Wo   = (const float*)d_in[6];
    float* out = (float*)d_out;

    __nv_bfloat16 *xh, *xl, *wh, *wl, *aoh, *aol;
    cudaGetSymbolAddress((void**)&xh,  g_xh);
    cudaGetSymbolAddress((void**)&xl,  g_xl);
    cudaGetSymbolAddress((void**)&wh,  g_wh);
    cudaGetSymbolAddress((void**)&wl,  g_wl);
    cudaGetSymbolAddress((void**)&aoh, g_aoh);
    cudaGetSymbolAddress((void**)&aol, g_aol);

    cudaFuncSetAttribute(attn_mma_kernel,
                         cudaFuncAttributeMaxDynamicSharedMemorySize, SMEM_ATTN);
    cudaFuncSetAttribute(gemm_mma_kernel<0>,
                         cudaFuncAttributeMaxDynamicSharedMemorySize, SMEM_GEMM);
    cudaFuncSetAttribute(gemm_mma_kernel<3>,
                         cudaFuncAttributeMaxDynamicSharedMemorySize, SMEM_GEMM);

    static cudaStream_t s1 = nullptr, s2 = nullptr;
    static cudaEvent_t ev_root = nullptr, ev_wqk = nullptr, ev_xb1 = nullptr,
                       ev_wo = nullptr, ev_q0 = nullptr, ev_s2 = nullptr;
    if (!s1) {
        cudaStreamCreateWithFlags(&s1, cudaStreamNonBlocking);
        cudaStreamCreateWithFlags(&s2, cudaStreamNonBlocking);
        cudaEventCreateWithFlags(&ev_root, cudaEventDisableTiming);
        cudaEventCreateWithFlags(&ev_wqk,  cudaEventDisableTiming);
        cudaEventCreateWithFlags(&ev_xb1,  cudaEventDisableTiming);
        cudaEventCreateWithFlags(&ev_wo,   cudaEventDisableTiming);
        cudaEventCreateWithFlags(&ev_q0,   cudaEventDisableTiming);
        cudaEventCreateWithFlags(&ev_s2,   cudaEventDisableTiming);
    }

    const size_t WSZ  = (size_t)GN * GK;
    const size_t XHALF = (size_t)(GM / 2) * GK;   // elements in one x half
    const int n4w = GN * GK / 4;
    const int n4h = (GM / 2) * GK / 4;            // float4s in one x half

    // ---- prologue ----
    cudaEventRecord(ev_root, 0);
    cudaStreamWaitEvent(s1, ev_root, 0);
    // s1: Wq, Wk (needed first), then x(b1) half, then Wo
    cvt_split_kernel<<<(n4w + 255) / 256, 256, 0, s1>>>(Wq, wh + 0 * WSZ, wl + 0 * WSZ, n4w);
    cvt_split_kernel<<<(n4w + 255) / 256, 256, 0, s1>>>(Wk, wh + 1 * WSZ, wl + 1 * WSZ, n4w);
    cudaEventRecord(ev_wqk, s1);
    cvt_split_kernel<<<(n4h + 255) / 256, 256, 0, s1>>>(x + XHALF, xh + XHALF, xl + XHALF, n4h);
    cudaEventRecord(ev_xb1, s1);
    cvt_split_kernel<<<(n4w + 255) / 256, 256, 0, s1>>>(Wo, wh + 3 * WSZ, wl + 3 * WSZ, n4w);
    cudaEventRecord(ev_wo, s1);
    // main: x(b0) half, Wv
    cvt_split_kernel<<<(n4h + 255) / 256, 256>>>(x, xh, xl, n4h);
    cvt_split_kernel<<<(n4w + 255) / 256, 256>>>(Wv, wh + 2 * WSZ, wl + 2 * WSZ, n4w);

    // ---- stage 1: QKV for batch 0 (rows 0..2047) ----
    cudaStreamWaitEvent(0, ev_wqk, 0);
    gemm_mma_kernel<3><<<dim3(3 * GN / 128, GM / 256), 256, SMEM_GEMM>>>(
        xh, xl, wh, wl, nullptr, cosb, sinb, 0);
    cudaEventRecord(ev_q0, 0);

    // ---- stage 2: QKV(b1) on main  ||  attn(b0) on s2 ----
    cudaStreamWaitEvent(0, ev_xb1, 0);
    gemm_mma_kernel<3><<<dim3(3 * GN / 128, GM / 256), 256, SMEM_GEMM>>>(
        xh, xl, wh, wl, nullptr, cosb, sinb, 2048);
    cudaStreamWaitEvent(s2, ev_q0, 0);
    attn_mma_kernel<<<dim3(CT / 128, CNH), 256, SMEM_ATTN, s2>>>(0);

    // ---- stage 3: attn(b1) on main  ||  Wo(b0 rows) on s2 ----
    attn_mma_kernel<<<dim3(CT / 128, CNH), 256, SMEM_ATTN>>>(1);
    cudaStreamWaitEvent(s2, ev_wo, 0);
    gemm_mma_kernel<0><<<dim3(GN / 128, GM / 256), 256, SMEM_GEMM, s2>>>(
        aoh, aol, wh + 3 * WSZ, wl + 3 * WSZ, out, nullptr, nullptr, 0);
    cudaEventRecord(ev_s2, s2);

    // ---- stage 4: Wo(b1 rows) on main, join ----
    cudaStreamWaitEvent(0, ev_wo, 0);
    gemm_mma_kernel<0><<<dim3(GN / 128, GM / 256), 256, SMEM_GEMM>>>(
        aoh, aol, wh + 3 * WSZ, wl + 3 * WSZ, out, nullptr, nullptr, 2048);
    cudaStreamWaitEvent(0, ev_s2, 0);
}

// round 16
// speedup vs baseline: 1.0678x; 1.0678x over previous
#include <cuda_runtime.h>
#include <cuda_bf16.h>
#include <cstdint>
#include <math.h>

// Problem constants
constexpr int CB  = 2;     // batch
constexpr int CT  = 2048;  // seq len
constexpr int CH  = 2048;  // hidden
constexpr int CNH = 16;    // heads
constexpr int CHD = 128;   // head dim
constexpr int GM  = CB * CT;   // 4096
constexpr int GK  = CH;        // 2048
constexpr int GN  = CH;        // 2048

// ---------------------------------------------------------------------------
// Scratch (allocation-free: __device__ globals)
// ---------------------------------------------------------------------------
__device__ __align__(16) __nv_bfloat16 g_xh [(size_t)GM * GK];
__device__ __align__(16) __nv_bfloat16 g_xl [(size_t)GM * GK];
__device__ __align__(16) __nv_bfloat16 g_wh [4][(size_t)GN * GK];  // q,k,v,o
__device__ __align__(16) __nv_bfloat16 g_wl [4][(size_t)GN * GK];
__device__ __align__(16) __nv_bfloat16 g_qh [(size_t)CB * CNH * CT * CHD];  // scaled
__device__ __align__(16) __nv_bfloat16 g_ql [(size_t)CB * CNH * CT * CHD];
__device__ __align__(16) __nv_bfloat16 g_kh [(size_t)CB * CNH * CT * CHD];
__device__ __align__(16) __nv_bfloat16 g_kl [(size_t)CB * CNH * CT * CHD];
__device__ __align__(16) __nv_bfloat16 g_vh [(size_t)CB * CNH * CT * CHD];
__device__ __align__(16) __nv_bfloat16 g_vl [(size_t)CB * CNH * CT * CHD];
__device__ __align__(16) __nv_bfloat16 g_aoh[(size_t)GM * GK];  // attn out [B*T][H]
__device__ __align__(16) __nv_bfloat16 g_aol[(size_t)GM * GK];

// ---------------------------------------------------------------------------
// Baseline-ISA helpers (all valid on compute_103 virtual arch)
// ---------------------------------------------------------------------------
__device__ __forceinline__ uint32_t smem_to_u32(const void* p) {
    uint32_t a;
    asm("{ .reg .u64 t; cvta.to.shared.u64 t, %1; cvt.u32.u64 %0, t; }"
        : "=r"(a) : "l"(p));
    return a;
}
__device__ __forceinline__ void ldmx4(uint32_t* r, uint32_t addr) {
    asm volatile("ldmatrix.sync.aligned.m8n8.x4.shared.b16 {%0,%1,%2,%3}, [%4];"
        : "=r"(r[0]), "=r"(r[1]), "=r"(r[2]), "=r"(r[3]) : "r"(addr));
}
__device__ __forceinline__ void ldmx4t(uint32_t* r, uint32_t addr) {
    asm volatile("ldmatrix.sync.aligned.m8n8.x4.trans.shared.b16 {%0,%1,%2,%3}, [%4];"
        : "=r"(r[0]), "=r"(r[1]), "=r"(r[2]), "=r"(r[3]) : "r"(addr));
}
__device__ __forceinline__ void mma16816(float* d, const uint32_t* a,
                                         const uint32_t* b) {
    asm volatile(
        "mma.sync.aligned.m16n8k16.row.col.f32.bf16.bf16.f32 "
        "{%0,%1,%2,%3}, {%4,%5,%6,%7}, {%8,%9}, {%0,%1,%2,%3};"
        : "+f"(d[0]), "+f"(d[1]), "+f"(d[2]), "+f"(d[3])
        : "r"(a[0]), "r"(a[1]), "r"(a[2]), "r"(a[3]), "r"(b[0]), "r"(b[1]));
}
__device__ __forceinline__ void cp_async16(uint32_t dst, const void* src) {
    asm volatile("cp.async.cg.shared.global [%0], [%1], 16;"
        :: "r"(dst), "l"(src));
}
#define CP_COMMIT() asm volatile("cp.async.commit_group;" ::: "memory")
#define CP_WAIT0()  asm volatile("cp.async.wait_group 0;" ::: "memory")

__device__ __forceinline__ uint32_t pack_bf16(float a, float b) {
    __nv_bfloat162 h = __float22bfloat162_rn(make_float2(a, b));
    return *(uint32_t*)&h;
}

// ---------------------------------------------------------------------------
// Split conversion: hi = bf16(x), lo = bf16(x - hi)
// ---------------------------------------------------------------------------
__global__ void cvt_split_kernel(const float* __restrict__ src,
                                 __nv_bfloat16* __restrict__ hi,
                                 __nv_bfloat16* __restrict__ lo, int n4)
{
    int i = blockIdx.x * blockDim.x + threadIdx.x;
    if (i >= n4) return;
    float4 v = ((const float4*)src)[i];
    __nv_bfloat16 h[4], l[4];
    h[0] = __float2bfloat16(v.x); l[0] = __float2bfloat16(v.x - __bfloat162float(h[0]));
    h[1] = __float2bfloat16(v.y); l[1] = __float2bfloat16(v.y - __bfloat162float(h[1]));
    h[2] = __float2bfloat16(v.z); l[2] = __float2bfloat16(v.z - __bfloat162float(h[2]));
    h[3] = __float2bfloat16(v.w); l[3] = __float2bfloat16(v.w - __bfloat162float(h[3]));
    *(uint2*)(hi + (size_t)i * 4) = *(uint2*)h;
    *(uint2*)(lo + (size_t)i * 4) = *(uint2*)l;
}

// ---------------------------------------------------------------------------
// GEMM Y = A @ B^T, split-bf16 3-pass, cp.async 2-stage, 2 CTAs/SM.
// MODE 0: fp32 row-major [GM][GN] (Wo -> out), rows offset by bm_off.
// MODE 3: fused QKV (N = 3*GN). Per-CTA proj = bn>>11:
//         Q/K -> acc staged via smem, RoPE applied (Q scaled), split-bf16
//                written into g_qh/ql/kh/kl [B,NH,T,HD];
//         V   -> split-bf16 direct into g_vh/vl.
// ---------------------------------------------------------------------------
constexpr int BKG = 32;
constexpr int ROWB = 80;                         // 64B data + 16 pad
constexpr int TILE_BYTES  = 128 * ROWB;          // 10240
constexpr int STAGE_BYTES = 4 * TILE_BYTES;      // Ah, Al, Bh, Bl
constexpr int SMEM_GEMM   = 2 * STAGE_BYTES;     // 81920 -> 2 CTAs/SM
constexpr int NKB = GK / BKG;                    // 64

template <int MODE>
__global__ __launch_bounds__(256, 2) void gemm_mma_kernel(
    const __nv_bfloat16* __restrict__ Ah, const __nv_bfloat16* __restrict__ Al,
    const __nv_bfloat16* __restrict__ Bh, const __nv_bfloat16* __restrict__ Bl,
    float* __restrict__ Y, const float* __restrict__ cosb,
    const float* __restrict__ sinb, int bm_off)
{
    extern __shared__ char sm[];
    const uint32_t sb = smem_to_u32(sm);
    const int tid = threadIdx.x;
    const int wid = tid >> 5, lid = tid & 31;
    const int wm = wid & 1, wn = wid >> 1;
    const int bn = blockIdx.x * 128, bm = blockIdx.y * 128 + bm_off;
    const int lg = lid >> 3, li = lid & 7;

    float acc[4][4][4];
#pragma unroll
    for (int mt = 0; mt < 4; mt++)
#pragma unroll
        for (int nt = 0; nt < 4; nt++)
#pragma unroll
            for (int r = 0; r < 4; r++) acc[mt][nt][r] = 0.f;

    auto issue_stage = [&](int s, int kb) {
#pragma unroll
        for (int i = 0; i < 8; i++) {
            int f = tid + i * 256;
            int pl = f >> 9, rem = f & 511, row = rem >> 2, c = rem & 3;
            const __nv_bfloat16* sp = (pl == 0) ? Ah : (pl == 1) ? Al
                                     : (pl == 2) ? Bh : Bl;
            int rbase = (pl >= 2) ? bn : bm;
            cp_async16(sb + s * STAGE_BYTES + pl * TILE_BYTES + row * ROWB + c * 16,
                       sp + (size_t)(rbase + row) * GK + kb * BKG + c * 8);
        }
    };

    issue_stage(0, 0); CP_COMMIT();

    for (int kb = 0; kb < NKB; kb++) {
        CP_WAIT0();
        __syncthreads();                  // stage kb ready; prev compute done
        if (kb + 1 < NKB) { issue_stage((kb + 1) & 1, kb + 1); CP_COMMIT(); }

        const uint32_t st = sb + (kb & 1) * STAGE_BYTES;
        const uint32_t sAh = st, sAl = st + TILE_BYTES;
        const uint32_t sBh = st + 2 * TILE_BYTES, sBl = st + 3 * TILE_BYTES;

#pragma unroll
        for (int ks = 0; ks < 2; ks++) {
            const int ko = ks * 32;
            const int aoff = ((lg & 1) * 8 + li) * ROWB + ko + (lg >> 1) * 16;
            const int boff = ((lg >> 1) * 8 + li) * ROWB + ko + (lg & 1) * 16;

            uint32_t ah[4][4], bh[4][2];
#pragma unroll
            for (int mt = 0; mt < 4; mt++)
                ldmx4(ah[mt], sAh + (wm * 64 + mt * 16) * ROWB + aoff);
#pragma unroll
            for (int p = 0; p < 2; p++) {
                uint32_t r[4];
                ldmx4(r, sBh + (wn * 32 + p * 16) * ROWB + boff);
                bh[2*p][0] = r[0]; bh[2*p][1] = r[1];
                bh[2*p+1][0] = r[2]; bh[2*p+1][1] = r[3];
            }
            // pass 1: Ah x Bh
#pragma unroll
            for (int mt = 0; mt < 4; mt++)
#pragma unroll
                for (int nt = 0; nt < 4; nt++)
                    mma16816(acc[mt][nt], ah[mt], bh[nt]);
            // pass 2: Al x Bh
            {
                uint32_t al[4][4];
#pragma unroll
                for (int mt = 0; mt < 4; mt++)
                    ldmx4(al[mt], sAl + (wm * 64 + mt * 16) * ROWB + aoff);
#pragma unroll
                for (int mt = 0; mt < 4; mt++)
#pragma unroll
                    for (int nt = 0; nt < 4; nt++)
                        mma16816(acc[mt][nt], al[mt], bh[nt]);
            }
            // pass 3: Ah x Bl
            {
                uint32_t bl[4][2];
#pragma unroll
                for (int p = 0; p < 2; p++) {
                    uint32_t r[4];
                    ldmx4(r, sBl + (wn * 32 + p * 16) * ROWB + boff);
                    bl[2*p][0] = r[0]; bl[2*p][1] = r[1];
                    bl[2*p+1][0] = r[2]; bl[2*p+1][1] = r[3];
                }
#pragma unroll
                for (int mt = 0; mt < 4; mt++)
#pragma unroll
                    for (int nt = 0; nt < 4; nt++)
                        mma16816(acc[mt][nt], ah[mt], bl[nt]);
            }
        }
    }

    const int er = lid >> 2;
    const int ec = (lid & 3) * 2;

    if (MODE == 0) {
#pragma unroll
        for (int mt = 0; mt < 4; mt++)
#pragma unroll
            for (int half = 0; half < 2; half++) {
                int row = bm + wm * 64 + mt * 16 + half * 8 + er;
                size_t base = (size_t)row * GN + bn;
#pragma unroll
                for (int nt = 0; nt < 4; nt++) {
                    int nc = wn * 32 + nt * 8 + ec;
                    *(float2*)(Y + base + nc) =
                        make_float2(acc[mt][nt][half * 2 + 0],
                                    acc[mt][nt][half * 2 + 1]);
                }
            }
    } else {  // MODE 3 fused QKV
        const int proj = bn >> 11;            // 0=Q, 1=K, 2=V (uniform per CTA)
        const int cn   = bn & (GN - 1);
        const int head = cn >> 7;
        if (proj == 2) {
#pragma unroll
            for (int mt = 0; mt < 4; mt++)
#pragma unroll
                for (int half = 0; half < 2; half++) {
                    int row = bm + wm * 64 + mt * 16 + half * 8 + er;
                    int b = row >> 11;
                    int t = row & (CT - 1);
                    size_t base = (((size_t)b * CNH + head) * CT + t) * CHD;
#pragma unroll
                    for (int nt = 0; nt < 4; nt++) {
                        int nc = wn * 32 + nt * 8 + ec;
                        float v0 = acc[mt][nt][half * 2 + 0];
                        float v1 = acc[mt][nt][half * 2 + 1];
                        __nv_bfloat162 h2 = __float22bfloat162_rn(make_float2(v0, v1));
                        *(uint32_t*)(g_vh + base + nc) = *(uint32_t*)&h2;
                        *(uint32_t*)(g_vl + base + nc) =
                            pack_bf16(v0 - __bfloat162float(h2.x),
                                      v1 - __bfloat162float(h2.y));
                    }
                }
        } else {
            // Q/K: stage fp32 tile in smem, apply RoPE, write split-bf16.
            float* smf = (float*)sm;          // [128][132] fp32 (67584 B)
            __syncthreads();                  // mainloop smem reads done
#pragma unroll
            for (int mt = 0; mt < 4; mt++)
#pragma unroll
                for (int half = 0; half < 2; half++) {
                    int rl = wm * 64 + mt * 16 + half * 8 + er;
#pragma unroll
                    for (int nt = 0; nt < 4; nt++) {
                        int cl = wn * 32 + nt * 8 + ec;
                        smf[rl * 132 + cl]     = acc[mt][nt][half * 2 + 0];
                        smf[rl * 132 + cl + 1] = acc[mt][nt][half * 2 + 1];
                    }
                }
            __syncthreads();
            const float scale = (proj == 0) ? 0.08838834764831843f : 1.f;
            __nv_bfloat16* Oh = (proj == 0) ? g_qh : g_kh;
            __nv_bfloat16* Ol = (proj == 0) ? g_ql : g_kl;
#pragma unroll
            for (int i = 0; i < 32; i++) {
                int idx = tid + i * 256;      // 8192 (row, d<64) pairs
                int rl = idx >> 6, d = idx & 63;
                int grow = bm + rl;
                int t = grow & (CT - 1), b = grow >> 11;
                float x0 = smf[rl * 132 + d];
                float x1 = smf[rl * 132 + d + 64];
                float c0 = cosb[t * CHD + d], c1 = cosb[t * CHD + d + 64];
                float s0 = sinb[t * CHD + d], s1 = sinb[t * CHD + d + 64];
                float ya = fmaf(x0, c0, -x1 * s0) * scale;
                float yb = fmaf(x1, c1,  x0 * s1) * scale;
                size_t base = (((size_t)b * CNH + head) * CT + t) * CHD;
                __nv_bfloat16 hh;
                hh = __float2bfloat16(ya);
                Oh[base + d] = hh;
                Ol[base + d] = __float2bfloat16(ya - __bfloat162float(hh));
                hh = __float2bfloat16(yb);
                Oh[base + d + 64] = hh;
                Ol[base + d + 64] = __float2bfloat16(yb - __bfloat162float(hh));
            }
        }
    }
}

// ---------------------------------------------------------------------------
// Tensor-core flash attention (causal). qt reversed (heavy first).
// Batch passed as param: b=0 and b=1 run as CONCURRENT launches on two
// streams (independent), letting main signal b0-done early for Wo overlap.
// ---------------------------------------------------------------------------
constexpr int KROWB    = 272;                    // 256B data + 16 pad
constexpr int KV_PLANE = 64 * KROWB;             // 17408
constexpr int KV_STAGE = 4 * KV_PLANE;           // kh,kl,vh,vl
constexpr int SMEM_ATTN = 2 * KV_STAGE;          // 139264

__global__ __launch_bounds__(256) void attn_mma_kernel(int bparam)
{
    extern __shared__ char sm[];
    const uint32_t sb = smem_to_u32(sm);
    const int qt = gridDim.x - 1 - blockIdx.x;   // heavy first
    const int h = blockIdx.y, b = bparam;
    const int tid = threadIdx.x, w = tid >> 5, l = tid & 31;
    const size_t bh = ((size_t)b * CNH + h) * CT * CHD;
    const int fr = l >> 2, t2 = (l & 3) * 2;
    const int lg = l >> 3, li = l & 7;

    const __nv_bfloat16* qhp = g_qh + bh + (size_t)(qt * 128 + w * 16) * CHD;
    const __nv_bfloat16* qlp = g_ql + bh + (size_t)(qt * 128 + w * 16) * CHD;
    uint32_t qhf[8][4];
#pragma unroll
    for (int ks = 0; ks < 8; ks++) {
        int c = ks * 16 + t2;
        qhf[ks][0] = *(const uint32_t*)(qhp + fr * 128 + c);
        qhf[ks][1] = *(const uint32_t*)(qhp + (fr + 8) * 128 + c);
        qhf[ks][2] = *(const uint32_t*)(qhp + fr * 128 + c + 8);
        qhf[ks][3] = *(const uint32_t*)(qhp + (fr + 8) * 128 + c + 8);
    }

    float o[16][4];
#pragma unroll
    for (int nt = 0; nt < 16; nt++)
#pragma unroll
        for (int e = 0; e < 4; e++) o[nt][e] = 0.f;
    float mx[2] = {-1e30f, -1e30f}, ls[2] = {0.f, 0.f};

    const int last = 2 * qt + 1;

    auto issue = [&](int s, int kt) {
        const __nv_bfloat16* srcs[4] = {
            g_kh + bh + (size_t)kt * 64 * CHD, g_kl + bh + (size_t)kt * 64 * CHD,
            g_vh + bh + (size_t)kt * 64 * CHD, g_vl + bh + (size_t)kt * 64 * CHD};
#pragma unroll
        for (int i = 0; i < 16; i++) {
            int f = tid + i * 256;
            int pl = f >> 10, rem = f & 1023, row = rem >> 4, c = rem & 15;
            cp_async16(sb + s * KV_STAGE + pl * KV_PLANE + row * KROWB + c * 16,
                       srcs[pl] + row * 128 + c * 8);
        }
    };

    issue(0, 0); CP_COMMIT();

    for (int kt = 0; kt <= last; kt++) {
        CP_WAIT0();
        __syncthreads();           // stage kt visible; all warps done with kt-1
        if (kt < last) { issue((kt + 1) & 1, kt + 1); CP_COMMIT(); }

        const uint32_t st = sb + (kt & 1) * KV_STAGE;
        const uint32_t kh_s = st, kl_s = st + KV_PLANE;
        const uint32_t vh_s = st + 2 * KV_PLANE, vl_s = st + 3 * KV_PLANE;

        // ---- S = Qs @ K^T (3 passes) ----
        float s4[8][4];
#pragma unroll
        for (int nt = 0; nt < 8; nt++)
#pragma unroll
            for (int e = 0; e < 4; e++) s4[nt][e] = 0.f;

        const int boffb = ((lg >> 1) * 8 + li) * KROWB + (lg & 1) * 16;
#pragma unroll
        for (int ks = 0; ks < 8; ks++) {
            uint32_t bf[8][2];
#pragma unroll
            for (int p = 0; p < 4; p++) {
                uint32_t r[4];
                ldmx4(r, kh_s + p * 16 * KROWB + ks * 32 + boffb);
                bf[2*p][0] = r[0]; bf[2*p][1] = r[1];
                bf[2*p+1][0] = r[2]; bf[2*p+1][1] = r[3];
            }
#pragma unroll
            for (int nt = 0; nt < 8; nt++) mma16816(s4[nt], qhf[ks], bf[nt]);
            uint32_t qlf[4];
            int c = ks * 16 + t2;
            qlf[0] = *(const uint32_t*)(qlp + fr * 128 + c);
            qlf[1] = *(const uint32_t*)(qlp + (fr + 8) * 128 + c);
            qlf[2] = *(const uint32_t*)(qlp + fr * 128 + c + 8);
            qlf[3] = *(const uint32_t*)(qlp + (fr + 8) * 128 + c + 8);
#pragma unroll
            for (int nt = 0; nt < 8; nt++) mma16816(s4[nt], qlf, bf[nt]);
        }
#pragma unroll
        for (int ks = 0; ks < 8; ks++) {
            uint32_t bf[8][2];
#pragma unroll
            for (int p = 0; p < 4; p++) {
                uint32_t r[4];
                ldmx4(r, kl_s + p * 16 * KROWB + ks * 32 + boffb);
                bf[2*p][0] = r[0]; bf[2*p][1] = r[1];
                bf[2*p+1][0] = r[2]; bf[2*p+1][1] = r[3];
            }
#pragma unroll
            for (int nt = 0; nt < 8; nt++) mma16816(s4[nt], qhf[ks], bf[nt]);
        }

        // ---- causal mask ----
        if (kt >= 2 * qt) {
            int row0 = qt * 128 + w * 16 + fr;
#pragma unroll
            for (int nt = 0; nt < 8; nt++) {
                int col0 = kt * 64 + nt * 8 + t2;
#pragma unroll
                for (int e = 0; e < 4; e++) {
                    int row = row0 + 8 * (e >> 1);
                    int col = col0 + (e & 1);
                    if (col > row) s4[nt][e] = -1e30f;
                }
            }
        }

        // ---- online softmax ----
#pragma unroll
        for (int half = 0; half < 2; half++) {
            float rm = -1e30f;
#pragma unroll
            for (int nt = 0; nt < 8; nt++)
                rm = fmaxf(rm, fmaxf(s4[nt][2*half], s4[nt][2*half+1]));
            rm = fmaxf(rm, __shfl_xor_sync(0xffffffffu, rm, 1));
            rm = fmaxf(rm, __shfl_xor_sync(0xffffffffu, rm, 2));
            float mn = fmaxf(mx[half], rm);
            float al = __expf(mx[half] - mn);
            mx[half] = mn;
            float rs = 0.f;
#pragma unroll
            for (int nt = 0; nt < 8; nt++) {
                s4[nt][2*half]   = __expf(s4[nt][2*half]   - mn);
                s4[nt][2*half+1] = __expf(s4[nt][2*half+1] - mn);
                rs += s4[nt][2*half] + s4[nt][2*half+1];
            }
            rs += __shfl_xor_sync(0xffffffffu, rs, 1);
            rs += __shfl_xor_sync(0xffffffffu, rs, 2);
            ls[half] = ls[half] * al + rs;
#pragma unroll
            for (int nt = 0; nt < 16; nt++) {
                o[nt][2*half]   *= al;
                o[nt][2*half+1] *= al;
            }
        }

        // ---- P fragments (hi/lo) ----
        uint32_t pha[4][4], pla[4][4];
#pragma unroll
        for (int kc = 0; kc < 4; kc++) {
#pragma unroll
            for (int j = 0; j < 4; j++) {
                int nt = 2 * kc + (j >> 1);
                int eb = (j & 1) * 2;
                float x0 = s4[nt][eb], x1 = s4[nt][eb + 1];
                __nv_bfloat162 h2 = __float22bfloat162_rn(make_float2(x0, x1));
                pha[kc][j] = *(uint32_t*)&h2;
                pla[kc][j] = pack_bf16(x0 - __bfloat162float(h2.x),
                                       x1 - __bfloat162float(h2.y));
            }
        }

        // ---- O += P @ V (3 passes) ----
#pragma unroll
        for (int kc = 0; kc < 4; kc++) {
            uint32_t vb[16][2];
#pragma unroll
            for (int p = 0; p < 8; p++) {
                uint32_t r[4];
                uint32_t addr = vh_s + (kc * 16 + (lg & 1) * 8 + li) * KROWB
                                + (p * 16 + (lg >> 1) * 8) * 2;
                ldmx4t(r, addr);
                vb[2*p][0] = r[0]; vb[2*p][1] = r[1];
                vb[2*p+1][0] = r[2]; vb[2*p+1][1] = r[3];
            }
#pragma unroll
            for (int nt = 0; nt < 16; nt++) mma16816(o[nt], pha[kc], vb[nt]);
#pragma unroll
            for (int nt = 0; nt < 16; nt++) mma16816(o[nt], pla[kc], vb[nt]);
#pragma unroll
            for (int p = 0; p < 8; p++) {
                uint32_t r[4];
                uint32_t addr = vl_s + (kc * 16 + (lg & 1) * 8 + li) * KROWB
                                + (p * 16 + (lg >> 1) * 8) * 2;
                ldmx4t(r, addr);
                vb[2*p][0] = r[0]; vb[2*p][1] = r[1];
                vb[2*p+1][0] = r[2]; vb[2*p+1][1] = r[3];
            }
#pragma unroll
            for (int nt = 0; nt < 16; nt++) mma16816(o[nt], pha[kc], vb[nt]);
        }
    }

    // ---- epilogue ----
    float inv0 = 1.f / ls[0], inv1 = 1.f / ls[1];
    int row0 = qt * 128 + w * 16 + fr;
    size_t r0 = ((size_t)b * CT + row0) * CH + h * CHD;
    size_t r1 = ((size_t)b * CT + row0 + 8) * CH + h * CHD;
#pragma unroll
    for (int nt = 0; nt < 16; nt++) {
        int col = nt * 8 + t2;
        float v0 = o[nt][0] * inv0, v1 = o[nt][1] * inv0;
        __nv_bfloat162 h2 = __float22bfloat162_rn(make_float2(v0, v1));
        *(uint32_t*)(g_aoh + r0 + col) = *(uint32_t*)&h2;
        *(uint32_t*)(g_aol + r0 + col) =
            pack_bf16(v0 - __bfloat162float(h2.x), v1 - __bfloat162float(h2.y));
        float v2 = o[nt][2] * inv1, v3 = o[nt][3] * inv1;
        __nv_bfloat162 h3 = __float22bfloat162_rn(make_float2(v2, v3));
        *(uint32_t*)(g_aoh + r1 + col) = *(uint32_t*)&h3;
        *(uint32_t*)(g_aol + r1 + col) =
            pack_bf16(v2 - __bfloat162float(h3.x), v3 - __bfloat162float(h3.y));
    }
}

// ---------------------------------------------------------------------------
// Launch — balanced prologue (cvts split across streams), fused QKV+RoPE,
// concurrent per-batch attention (main: b0, s2: b1), per-batch Wo with
// Wo(b0) backfilling while attn(b1) drains.   [R14-validated configuration]
// ---------------------------------------------------------------------------
extern "C" void kernel_launch(void* const* d_in, const int* in_sizes, int n_in,
                              void* d_out, int out_size)
{
    (void)in_sizes; (void)n_in; (void)out_size;
    const float* x    = (const float*)d_in[0];
    const float* cosb = (const float*)d_in[1];
    const float* sinb = (const float*)d_in[2];
    const float* Wq   = (const float*)d_in[3];
    const float* Wk   = (const float*)d_in[4];
    const float* Wv   = (const float*)d_in[5];
    const float* Wo   = (const float*)d_in[6];
    float* out = (float*)d_out;

    __nv_bfloat16 *xh, *xl, *wh, *wl, *aoh, *aol;
    cudaGetSymbolAddress((void**)&xh,  g_xh);
    cudaGetSymbolAddress((void**)&xl,  g_xl);
    cudaGetSymbolAddress((void**)&wh,  g_wh);
    cudaGetSymbolAddress((void**)&wl,  g_wl);
    cudaGetSymbolAddress((void**)&aoh, g_aoh);
    cudaGetSymbolAddress((void**)&aol, g_aol);

    cudaFuncSetAttribute(attn_mma_kernel,
                         cudaFuncAttributeMaxDynamicSharedMemorySize, SMEM_ATTN);
    cudaFuncSetAttribute(gemm_mma_kernel<0>,
                         cudaFuncAttributeMaxDynamicSharedMemorySize, SMEM_GEMM);
    cudaFuncSetAttribute(gemm_mma_kernel<3>,
                         cudaFuncAttributeMaxDynamicSharedMemorySize, SMEM_GEMM);

    static cudaStream_t s1 = nullptr, s2 = nullptr;
    static cudaEvent_t ev_root = nullptr, ev_wqk = nullptr, ev_wo = nullptr,
                       ev_qkv = nullptr, ev_s2 = nullptr;
    if (!s1) {
        cudaStreamCreateWithFlags(&s1, cudaStreamNonBlocking);
        cudaStreamCreateWithFlags(&s2, cudaStreamNonBlocking);
        cudaEventCreateWithFlags(&ev_root, cudaEventDisableTiming);
        cudaEventCreateWithFlags(&ev_wqk,  cudaEventDisableTiming);
        cudaEventCreateWithFlags(&ev_wo,   cudaEventDisableTiming);
        cudaEventCreateWithFlags(&ev_qkv,  cudaEventDisableTiming);
        cudaEventCreateWithFlags(&ev_s2,   cudaEventDisableTiming);
    }

    const size_t WSZ = (size_t)GN * GK;
    const int n4x = GM * GK / 4;
    const int n4w = GN * GK / 4;

    // Balanced prologue: main does x + Wv (2 kernels), s1 does Wq + Wk + Wo.
    cudaEventRecord(ev_root, 0);
    cudaStreamWaitEvent(s1, ev_root, 0);
    cvt_split_kernel<<<(n4w + 255) / 256, 256, 0, s1>>>(Wq, wh + 0 * WSZ, wl + 0 * WSZ, n4w);
    cvt_split_kernel<<<(n4w + 255) / 256, 256, 0, s1>>>(Wk, wh + 1 * WSZ, wl + 1 * WSZ, n4w);
    cudaEventRecord(ev_wqk, s1);
    cvt_split_kernel<<<(n4w + 255) / 256, 256, 0, s1>>>(Wo, wh + 3 * WSZ, wl + 3 * WSZ, n4w);
    cudaEventRecord(ev_wo, s1);

    cvt_split_kernel<<<(n4x + 255) / 256, 256>>>(x, xh, xl, n4x);
    cvt_split_kernel<<<(n4w + 255) / 256, 256>>>(Wv, wh + 2 * WSZ, wl + 2 * WSZ, n4w);

    // fused QKV GEMM (RoPE in epilogue); needs x,Wv (stream order) + Wq,Wk (event)
    cudaStreamWaitEvent(0, ev_wqk, 0);
    gemm_mma_kernel<3><<<dim3(3 * GN / 128, GM / 128), 256, SMEM_GEMM>>>(
        xh, xl, wh, wl, nullptr, cosb, sinb, 0);
    cudaEventRecord(ev_qkv, 0);

    // attention: b=0 on main, b=1 on s2 (concurrent, independent)
    cudaStreamWaitEvent(s2, ev_qkv, 0);
    attn_mma_kernel<<<dim3(CT / 128, CNH), 256, SMEM_ATTN>>>(0);
    attn_mma_kernel<<<dim3(CT / 128, CNH), 256, SMEM_ATTN, s2>>>(1);

    // Wo(b0 rows) on main right after attn(b0) -> backfills as attn(b1) drains
    cudaStreamWaitEvent(0, ev_wo, 0);
    gemm_mma_kernel<0><<<dim3(GN / 128, GM / 256), 256, SMEM_GEMM>>>(
        aoh, aol, wh + 3 * WSZ, wl + 3 * WSZ, out, nullptr, nullptr, 0);

    // Wo(b1 rows) on s2 after attn(b1)
    cudaStreamWaitEvent(s2, ev_wo, 0);
    gemm_mma_kernel<0><<<dim3(GN / 128, GM / 256), 256, SMEM_GEMM, s2>>>(
        aoh, aol, wh + 3 * WSZ, wl + 3 * WSZ, out, nullptr, nullptr, 2048);
    cudaEventRecord(ev_s2, s2);

    // join
    cudaStreamWaitEvent(0, ev_s2, 0);
}